// round 13
// baseline (speedup 1.0000x reference)
#include <cuda_runtime.h>
#include <math.h>

#define B_ 64
#define L_ 512
#define E_ 64
#define H_ 8
#define D_ 8
#define ROWS (B_*L_)          // 32768
#define QK_SCALE 0.35355339059327373f   // 1/sqrt(8)
#define LOG2E_F  1.4426950408889634f
#define NSL1 4                // key slices for pass1 (denominators)
#define SLK1 (L_/NSL1)        // 128 keys
#define NSL2 2                // key slices for pass2 (ctx partials)
#define SLK2 (L_/NSL2)        // 256 keys

typedef unsigned long long u64t;

// ---- packed f32x2 helpers (ptxas never auto-fuses; PTX only) ----
__device__ __forceinline__ u64t fma2(u64t a, u64t b, u64t c) {
    u64t d; asm("fma.rn.f32x2 %0, %1, %2, %3;" : "=l"(d) : "l"(a), "l"(b), "l"(c)); return d;
}
__device__ __forceinline__ u64t mul2(u64t a, u64t b) {
    u64t d; asm("mul.rn.f32x2 %0, %1, %2;" : "=l"(d) : "l"(a), "l"(b)); return d;
}
__device__ __forceinline__ u64t pack2(float lo, float hi) {
    u64t d; asm("mov.b64 %0, {%1, %2};" : "=l"(d) : "f"(lo), "f"(hi)); return d;
}
__device__ __forceinline__ void unpack2(u64t a, float& lo, float& hi) {
    asm("mov.b64 {%0, %1}, %2;" : "=f"(lo), "=f"(hi) : "l"(a));
}
__device__ __forceinline__ float ex2f(float x) {
    float r; asm("ex2.approx.f32 %0, %1;" : "=f"(r) : "f"(x)); return r;
}
__device__ __forceinline__ float lg2f(float x) {
    float r; asm("lg2.approx.f32 %0, %1;" : "=f"(r) : "f"(x)); return r;
}
__device__ __forceinline__ void barpair(int id) {
    asm volatile("bar.sync %0, 64;" :: "r"(id) : "memory");
}

// ---- scratch (static device arrays; no allocation) ----
__device__ float g_qh  [ROWS*E_];
__device__ float g_kh  [ROWS*E_];
__device__ float g_vh  [ROWS*E_];
__device__ float g_x   [ROWS*E_];
__device__ float g_p1  [ROWS*NSL1*H_];    // per-slice denominator partials
__device__ float g_ctxp[NSL2*ROWS*E_];    // per-slice ctx partials (16MB)

// ---------------------------------------------------------------------------
// GEMM compute core: xs[32][68], Ws[64][68] staged; 4x4 tile per thread,
// LDS.128 j-quad inner loop, packed fma2, 32-reg accumulators.
// ---------------------------------------------------------------------------
__device__ __forceinline__ void gemm_core(
    const float (*xs)[68], const float (*Ws)[68], int tx, int ty,
    u64t acc2[4][4])
{
#pragma unroll
    for (int rr = 0; rr < 4; rr++)
#pragma unroll
        for (int c = 0; c < 4; c++) acc2[rr][c] = 0ull;

#pragma unroll 4
    for (int j4 = 0; j4 < 16; j4++) {
        ulonglong2 xv[4], wv[4];
#pragma unroll
        for (int rr = 0; rr < 4; rr++)
            xv[rr] = *(const ulonglong2*)&xs[ty * 4 + rr][4 * j4];
#pragma unroll
        for (int c = 0; c < 4; c++)
            wv[c] = *(const ulonglong2*)&Ws[tx + c * 16][4 * j4];
#pragma unroll
        for (int rr = 0; rr < 4; rr++)
#pragma unroll
            for (int c = 0; c < 4; c++) {
                acc2[rr][c] = fma2(xv[rr].x, wv[c].x, acc2[rr][c]);
                acc2[rr][c] = fma2(xv[rr].y, wv[c].y, acc2[rr][c]);
            }
    }
}

// ---------------------------------------------------------------------------
// Fused q/k/v projection: blockIdx.y picks (X, W, bias, out, scale).
// W rows permuted at staging so output lands directly in [d*8+h] attn
// layout with coalesced stores. q pre-scaled by QK_SCALE*log2(e).
// ---------------------------------------------------------------------------
__global__ __launch_bounds__(128) void proj3(
    const float* __restrict__ q, const float* __restrict__ k,
    const float* __restrict__ Wq, const float* __restrict__ bq,
    const float* __restrict__ Wk, const float* __restrict__ bk,
    const float* __restrict__ Wv, const float* __restrict__ bv,
    float* __restrict__ qh, float* __restrict__ kh, float* __restrict__ vh)
{
    __shared__ float xs[32][68];
    __shared__ float Ws[64][68];

    const int t = threadIdx.x;
    const int which = blockIdx.y;
    const int rowbase = blockIdx.x * 32;

    const float* X    = (which == 0) ? q  : k;
    const float* W    = (which == 0) ? Wq : (which == 1) ? Wk : Wv;
    const float* bias = (which == 0) ? bq : (which == 1) ? bk : bv;
    float* Y          = (which == 0) ? qh : (which == 1) ? kh : vh;
    const float scale = (which == 0) ? QK_SCALE * LOG2E_F : 1.0f;

#pragma unroll
    for (int j = 0; j < 4; j++) {
        int fidx = t + j * 128;                  // 0..511
        int r = fidx >> 4, c = (fidx & 15) * 4;
        *(float4*)&xs[r][c] = ((const float4*)(X + (size_t)rowbase * 64))[fidx];
    }
    // Ws[r] = W[perm(r)]; perm(r) = (r&7)*8 + (r>>3)  (64B-coalesced loads)
#pragma unroll
    for (int j = 0; j < 8; j++) {
        int fidx = t + j * 128;                  // 0..1023
        int r = fidx >> 4, c = fidx & 15;
        int pr = (r & 7) * 8 + (r >> 3);
        *(float4*)&Ws[r][c * 4] = ((const float4*)W)[pr * 16 + c];
    }
    __syncthreads();

    const int tx = t & 15;
    const int ty = t >> 4;
    u64t acc2[4][4];
    gemm_core(xs, Ws, tx, ty, acc2);

#pragma unroll
    for (int c = 0; c < 4; c++) {
        int col = tx + c * 16;                   // already attn-layout column
        float bb = bias[(col & 7) * 8 + (col >> 3)];
#pragma unroll
        for (int rr = 0; rr < 4; rr++) {
            float lo, hi; unpack2(acc2[rr][c], lo, hi);
            Y[(size_t)(rowbase + ty * 4 + rr) * 64 + col] =
                scale * ((lo + hi) + bb);
        }
    }
}

// ---------------------------------------------------------------------------
// Fused GEMM + residual add + LayerNorm (Wo/ln1 path).
// out[r] = LN( sum_slices(ctxp)[r] @ W^T + bias + resid[r] )
// W's j index permuted at staging ([d*8+h] inputs).
// ---------------------------------------------------------------------------
__global__ __launch_bounds__(128) void gemm_ln(
    const float* __restrict__ X, const float* __restrict__ W,
    const float* __restrict__ bias, const float* __restrict__ resid,
    const float* __restrict__ g, const float* __restrict__ beta,
    float* __restrict__ out)
{
    __shared__ float xs[32][68];
    __shared__ float Ws[64][68];
    __shared__ float red[32][8];

    const int t = threadIdx.x;
    const int rowbase = blockIdx.x * 32;

    // xs[r][c] = sum over NSL2 slices of ctxp  (float4 granularity)
#pragma unroll
    for (int j = 0; j < 4; j++) {
        int fidx = t + j * 128;                  // 0..511 float4s
        size_t gf = (size_t)rowbase * 16 + fidx;
        float4 s = ((const float4*)X)[gf];
#pragma unroll
        for (int ss = 1; ss < NSL2; ss++) {
            float4 a = ((const float4*)X)[(size_t)ss * ROWS * 16 + gf];
            s.x += a.x; s.y += a.y; s.z += a.z; s.w += a.w;
        }
        int r = fidx >> 4, c = (fidx & 15) * 4;
        *(float4*)&xs[r][c] = s;
    }
    // W with permuted j (scalar gather)
#pragma unroll
    for (int kk = 0; kk < 32; kk++) {
        int idx = t + kk * 128;
        int r = idx >> 6, c = idx & 63;
        int cc = (c & 7) * 8 + (c >> 3);
        Ws[r][c] = W[r * 64 + cc];
    }
    __syncthreads();

    const int tx = t & 15;
    const int ty = t >> 4;
    u64t acc2[4][4];
    gemm_core(xs, Ws, tx, ty, acc2);

    __syncthreads();   // done reading xs; reuse it for the pre-LN values
#pragma unroll
    for (int c = 0; c < 4; c++) {
        int col = tx + c * 16;
        float bb = bias[col];
#pragma unroll
        for (int rr = 0; rr < 4; rr++) {
            float lo, hi; unpack2(acc2[rr][c], lo, hi);
            int row = ty * 4 + rr;
            xs[row][col] = (lo + hi) + bb +
                           resid[(size_t)(rowbase + row) * 64 + col];
        }
    }
    __syncthreads();

    // LN over each row of 64: 4 threads per row, 16 cols each
    const int row  = t >> 2;
    const int part = t & 3;
    float lsum = 0.0f, lsq = 0.0f;
#pragma unroll
    for (int j = 0; j < 16; j++) {
        float v = xs[row][part * 16 + j];
        lsum += v;
        lsq  = fmaf(v, v, lsq);
    }
    red[row][part]     = lsum;
    red[row][part + 4] = lsq;
    __syncthreads();

    float s  = red[row][0] + red[row][1] + red[row][2] + red[row][3];
    float sq = red[row][4] + red[row][5] + red[row][6] + red[row][7];
    float mu   = s * (1.0f / 64.0f);
    float var  = sq * (1.0f / 64.0f) - mu * mu;
    float rstd = rsqrtf(var + 1e-5f);

    float4 o[4];
#pragma unroll
    for (int j = 0; j < 16; j++) {
        int c = part * 16 + j;
        ((float*)o)[j] = fmaf((xs[row][c] - mu) * rstd, g[c], beta[c]);
    }
    float4* op = (float4*)(out + (size_t)(rowbase + row) * 64 + part * 16);
#pragma unroll
    for (int j = 0; j < 4; j++) op[j] = o[j];
}

// ---------------------------------------------------------------------------
// Fully fused FFN: out = LN2( relu(x@W1^T + b1) @ W2^T + b2 + x )
// One block = 32 rows. x, W1, W2 all staged up front; f1 lives only in smem.
// Saves the f1 global round-trip, the x re-read, and one launch.
// ---------------------------------------------------------------------------
__global__ __launch_bounds__(128) void ffn_fused(
    const float* __restrict__ X, const float* __restrict__ W1,
    const float* __restrict__ b1, const float* __restrict__ W2,
    const float* __restrict__ b2, const float* __restrict__ g,
    const float* __restrict__ beta, float* __restrict__ out)
{
    __shared__ float xs [32][68];
    __shared__ float fs [32][68];
    __shared__ float Ws1[64][68];
    __shared__ float Ws2[64][68];
    __shared__ float red[32][8];

    const int t = threadIdx.x;
    const int rowbase = blockIdx.x * 32;

#pragma unroll
    for (int j = 0; j < 4; j++) {
        int fidx = t + j * 128;
        int r = fidx >> 4, c = (fidx & 15) * 4;
        *(float4*)&xs[r][c] = ((const float4*)(X + (size_t)rowbase * 64))[fidx];
    }
#pragma unroll
    for (int j = 0; j < 8; j++) {
        int fidx = t + j * 128;
        int r = fidx >> 4, c = (fidx & 15) * 4;
        *(float4*)&Ws1[r][c] = ((const float4*)W1)[fidx];
        *(float4*)&Ws2[r][c] = ((const float4*)W2)[fidx];
    }
    __syncthreads();

    const int tx = t & 15;
    const int ty = t >> 4;
    u64t acc2[4][4];

    // f1 = relu(x @ W1^T + b1)  -> fs
    gemm_core(xs, Ws1, tx, ty, acc2);
#pragma unroll
    for (int c = 0; c < 4; c++) {
        int col = tx + c * 16;
        float bb = b1[col];
#pragma unroll
        for (int rr = 0; rr < 4; rr++) {
            float lo, hi; unpack2(acc2[rr][c], lo, hi);
            fs[ty * 4 + rr][col] = fmaxf((lo + hi) + bb, 0.0f);
        }
    }
    __syncthreads();

    // y = f1 @ W2^T + b2 + x   -> fs (after all reads complete)
    gemm_core(fs, Ws2, tx, ty, acc2);
    __syncthreads();
#pragma unroll
    for (int c = 0; c < 4; c++) {
        int col = tx + c * 16;
        float bb = b2[col];
#pragma unroll
        for (int rr = 0; rr < 4; rr++) {
            float lo, hi; unpack2(acc2[rr][c], lo, hi);
            int row = ty * 4 + rr;
            fs[row][col] = (lo + hi) + bb + xs[row][col];
        }
    }
    __syncthreads();

    // LN over each row of 64: 4 threads per row, 16 cols each
    const int row  = t >> 2;
    const int part = t & 3;
    float lsum = 0.0f, lsq = 0.0f;
#pragma unroll
    for (int j = 0; j < 16; j++) {
        float v = fs[row][part * 16 + j];
        lsum += v;
        lsq  = fmaf(v, v, lsq);
    }
    red[row][part]     = lsum;
    red[row][part + 4] = lsq;
    __syncthreads();

    float s  = red[row][0] + red[row][1] + red[row][2] + red[row][3];
    float sq = red[row][4] + red[row][5] + red[row][6] + red[row][7];
    float mu   = s * (1.0f / 64.0f);
    float var  = sq * (1.0f / 64.0f) - mu * mu;
    float rstd = rsqrtf(var + 1e-5f);

    float4 o[4];
#pragma unroll
    for (int j = 0; j < 16; j++) {
        int c = part * 16 + j;
        ((float*)o)[j] = fmaf((fs[row][c] - mu) * rstd, g[c], beta[c]);
    }
    float4* op = (float4*)(out + (size_t)(rowbase + row) * 64 + part * 16);
#pragma unroll
    for (int j = 0; j < 4; j++) op[j] = o[j];
}

// ---------------------------------------------------------------------------
// Attention pass 1: per-slice softmax denominator partials.
// Block 128 thr = 4 warps: warp = qg*2 + hh. Lane owns TWO queries, 4 heads.
// Whole 128-key slice staged once (32KB). Grid (L/128, NSL1, B).
// ---------------------------------------------------------------------------
__global__ __launch_bounds__(128) void attn_pass1(
    const float* __restrict__ qh, const float* __restrict__ kh,
    float* __restrict__ part)
{
    __shared__ float Ks[SLK1 * 64];   // 32KB

    const int b    = blockIdx.z;
    const int sl   = blockIdx.y;
    const int tid  = threadIdx.x;
    const int warp = tid >> 5;
    const int lane = tid & 31;
    const int qg   = warp >> 1;
    const int hh   = warp & 1;
    const size_t qi0 = (size_t)b * L_ + blockIdx.x * 128 + qg * 64 + lane;
    const size_t qi1 = qi0 + 32;

    u64t qa[16], qb[16];
    {
        const float* qp0 = qh + qi0 * 64 + hh * 4;
        const float* qp1 = qh + qi1 * 64 + hh * 4;
#pragma unroll
        for (int d = 0; d < 8; d++) {
            ulonglong2 v0 = *(const ulonglong2*)(qp0 + d * 8);
            ulonglong2 v1 = *(const ulonglong2*)(qp1 + d * 8);
            qa[2 * d] = v0.x; qa[2 * d + 1] = v0.y;
            qb[2 * d] = v1.x; qb[2 * d + 1] = v1.y;
        }
    }

    {
        const float4* src =
            (const float4*)(kh + ((size_t)b * L_ + sl * SLK1) * 64);
        float4* dst = (float4*)Ks;
#pragma unroll
        for (int j = 0; j < 16; j++)
            dst[tid + j * 128] = src[tid + j * 128];
    }
    __syncthreads();

    float sa[4] = {0.0f, 0.0f, 0.0f, 0.0f};
    float sb[4] = {0.0f, 0.0f, 0.0f, 0.0f};

#pragma unroll 2
    for (int m = 0; m < SLK1; m++) {
        const float* krow = Ks + m * 64 + hh * 4;
        u64t a0, a1, b0, b1;
        {
            ulonglong2 kd = *(const ulonglong2*)krow;
            a0 = mul2(qa[0], kd.x); a1 = mul2(qa[1], kd.y);
            b0 = mul2(qb[0], kd.x); b1 = mul2(qb[1], kd.y);
        }
#pragma unroll
        for (int d = 1; d < 8; d++) {
            ulonglong2 kd = *(const ulonglong2*)(krow + d * 8);
            a0 = fma2(qa[2 * d],     kd.x, a0);
            a1 = fma2(qa[2 * d + 1], kd.y, a1);
            b0 = fma2(qb[2 * d],     kd.x, b0);
            b1 = fma2(qb[2 * d + 1], kd.y, b1);
        }
        float lo, hi;
        unpack2(a0, lo, hi); sa[0] += ex2f(lo); sa[1] += ex2f(hi);
        unpack2(a1, lo, hi); sa[2] += ex2f(lo); sa[3] += ex2f(hi);
        unpack2(b0, lo, hi); sb[0] += ex2f(lo); sb[1] += ex2f(hi);
        unpack2(b1, lo, hi); sb[2] += ex2f(lo); sb[3] += ex2f(hi);
    }

    ((float4*)(part + qi0 * (NSL1 * 8) + sl * 8 + hh * 4))[0] =
        make_float4(sa[0], sa[1], sa[2], sa[3]);
    ((float4*)(part + qi1 * (NSL1 * 8) + sl * 8 + hh * 4))[0] =
        make_float4(sb[0], sb[1], sb[2], sb[3]);
}

// ---------------------------------------------------------------------------
// Attention pass 2: per-slice NORMALIZED ctx partials + fp32 attn_wts.
// warp = qg*2 + hh; lane owns one query, 4 heads. li = -log2(denom) folded
// into QK accumulator init => ex2 yields normalized p. 64-key K+V tiles.
// NSL2=2 slices (256 keys each). Head-half combine for attn_wts per
// warp-PAIR with 64-thread named barriers.
// ---------------------------------------------------------------------------
__global__ __launch_bounds__(256) void attn_pass2(
    const float* __restrict__ qh, const float* __restrict__ kh,
    const float* __restrict__ vh, const float* __restrict__ part,
    float* __restrict__ ctxp, float* __restrict__ attn_out)
{
    __shared__ float Ks[64 * 64];          // 16KB
    __shared__ float Vs[64 * 64];          // 16KB
    __shared__ float Wtile[8][32][17];     // 17.4KB

    const int b    = blockIdx.z;
    const int sl   = blockIdx.y;
    const int tid  = threadIdx.x;
    const int warp = tid >> 5;
    const int lane = tid & 31;
    const int qg   = warp >> 1;
    const int hh   = warp & 1;
    const int lt   = tid & 63;             // id within warp-pair
    const size_t qi = (size_t)b * L_ + blockIdx.x * 128 + qg * 32 + lane;

    u64t q2[16];
    {
        const float* qp = qh + qi * 64 + hh * 4;
#pragma unroll
        for (int d = 0; d < 8; d++) {
            ulonglong2 v = *(const ulonglong2*)(qp + d * 8);
            q2[2 * d] = v.x; q2[2 * d + 1] = v.y;
        }
    }

    u64t li2[2];
    {
        float s[4] = {0.0f, 0.0f, 0.0f, 0.0f};
        const float4* pp = (const float4*)(part + qi * (NSL1 * 8));
#pragma unroll
        for (int ss = 0; ss < NSL1; ss++) {
            float4 a = pp[2 * ss + hh];
            s[0] += a.x; s[1] += a.y; s[2] += a.z; s[3] += a.w;
        }
        li2[0] = pack2(-lg2f(s[0]), -lg2f(s[1]));
        li2[1] = pack2(-lg2f(s[2]), -lg2f(s[3]));
    }

    u64t ctx2[16];
#pragma unroll
    for (int j = 0; j < 16; j++) ctx2[j] = 0ull;

    for (int t = 0; t < SLK2 / 64; t++) {
        __syncthreads();
        {
            const size_t rowb = ((size_t)b * L_ + sl * SLK2 + t * 64) * 16;
            const float4* ksrc = (const float4*)kh + rowb;
            const float4* vsrc = (const float4*)vh + rowb;
            float4* kdst = (float4*)Ks;
            float4* vdst = (float4*)Vs;
#pragma unroll
            for (int j = 0; j < 4; j++) {
                kdst[tid + j * 256] = ksrc[tid + j * 256];
                vdst[tid + j * 256] = vsrc[tid + j * 256];
            }
        }
        __syncthreads();

        for (int chunk = 0; chunk < 4; chunk++) {
#pragma unroll 4
            for (int mm = 0; mm < 16; mm++) {
                const int m = chunk * 16 + mm;
                const float* krow = Ks + m * 64 + hh * 4;
                u64t acc0 = li2[0], acc1 = li2[1];
#pragma unroll
                for (int d = 0; d < 8; d++) {
                    ulonglong2 kd = *(const ulonglong2*)(krow + d * 8);
                    acc0 = fma2(q2[2 * d],     kd.x, acc0);
                    acc1 = fma2(q2[2 * d + 1], kd.y, acc1);
                }
                float e0, e1, e2v, e3v;
                { float lo, hi; unpack2(acc0, lo, hi); e0 = ex2f(lo); e1 = ex2f(hi); }
                { float lo, hi; unpack2(acc1, lo, hi); e2v = ex2f(lo); e3v = ex2f(hi); }
                Wtile[warp][lane][mm] = (e0 + e1) + (e2v + e3v);

                u64t ep0 = pack2(e0, e1), ep1 = pack2(e2v, e3v);
                const float* vrow = Vs + m * 64 + hh * 4;
#pragma unroll
                for (int d = 0; d < 8; d++) {
                    ulonglong2 vd = *(const ulonglong2*)(vrow + d * 8);
                    ctx2[2 * d]     = fma2(ep0, vd.x, ctx2[2 * d]);
                    ctx2[2 * d + 1] = fma2(ep1, vd.y, ctx2[2 * d + 1]);
                }
            }
            // pair-combine hh halves -> fp32 attn_out (64-thread barrier)
            barpair(1 + qg);
            {
                const int m0 = sl * SLK2 + t * 64 + chunk * 16;
                const size_t row0 = (size_t)b * L_ + blockIdx.x * 128 + qg * 32;
#pragma unroll
                for (int it = 0; it < 8; it++) {
                    int idx = lt + it * 64;             // 0..511
                    int c   = idx & 15;
                    int r   = idx >> 4;                 // 0..31
                    float w = (Wtile[qg * 2][r][c] + Wtile[qg * 2 + 1][r][c])
                              * 0.125f;
                    attn_out[(row0 + r) * L_ + m0 + c] = w;
                }
            }
            barpair(1 + qg);
        }
    }

    // store this half's normalized ctx partial (disjoint 16B chunks)
    float* cb = ctxp + (size_t)sl * ROWS * 64 + qi * 64 + hh * 4;
#pragma unroll
    for (int d = 0; d < 8; d++) {
        ulonglong2 v;
        v.x = ctx2[2 * d]; v.y = ctx2[2 * d + 1];
        *(ulonglong2*)(cb + d * 8) = v;
    }
}

// ---------------------------------------------------------------------------
extern "C" void kernel_launch(void* const* d_in, const int* in_sizes, int n_in,
                              void* d_out, int out_size)
{
    const float* q    = (const float*)d_in[0];
    const float* k    = (const float*)d_in[1];
    const float* prev = (const float*)d_in[2];
    const float* Wq   = (const float*)d_in[3];
    const float* bq   = (const float*)d_in[4];
    const float* Wk   = (const float*)d_in[5];
    const float* bk   = (const float*)d_in[6];
    const float* Wv   = (const float*)d_in[7];
    const float* bv   = (const float*)d_in[8];
    const float* Wo   = (const float*)d_in[9];
    const float* bo   = (const float*)d_in[10];
    const float* g1   = (const float*)d_in[11];
    const float* be1  = (const float*)d_in[12];
    const float* W1   = (const float*)d_in[13];
    const float* b1   = (const float*)d_in[14];
    const float* W2   = (const float*)d_in[15];
    const float* b2   = (const float*)d_in[16];
    const float* g2   = (const float*)d_in[17];
    const float* be2  = (const float*)d_in[18];

    float* outp = (float*)d_out;                    // [B, Lq, E]
    float* attn = outp + (size_t)ROWS * E_;         // [B, Lq, Lk]

    float *qh, *khp, *vhp, *xbuf, *p1, *ctxp;
    cudaGetSymbolAddress((void**)&qh,  g_qh);
    cudaGetSymbolAddress((void**)&khp, g_kh);
    cudaGetSymbolAddress((void**)&vhp, g_vh);
    cudaGetSymbolAddress((void**)&xbuf,g_x);
    cudaGetSymbolAddress((void**)&p1,  g_p1);
    cudaGetSymbolAddress((void**)&ctxp,g_ctxp);

    const int GB = ROWS / 32;   // 1024 blocks per gemm

    // fused q/k/v projections (one launch, 3072 blocks)
    proj3<<<dim3(GB, 3), 128>>>(q, k, Wq, bq, Wk, bk, Wv, bv, qh, khp, vhp);

    attn_pass1<<<dim3(L_ / 128, NSL1, B_), 128>>>(qh, khp, p1);
    attn_pass2<<<dim3(L_ / 128, NSL2, B_), 256>>>(qh, khp, vhp, p1, ctxp, attn);

    // Wo GEMM + ctx_combine + residual(prev) + LN1  -> xbuf
    gemm_ln<<<GB, 128>>>(ctxp, Wo, bo, prev, g1, be1, xbuf);

    // fully fused FFN + residual + LN2 -> final out
    ffn_fused<<<GB, 128>>>(xbuf, W1, b1, W2, b2, g2, be2, outp);
}

// round 14
// speedup vs baseline: 1.0943x; 1.0943x over previous
#include <cuda_runtime.h>
#include <math.h>

#define B_ 64
#define L_ 512
#define E_ 64
#define H_ 8
#define D_ 8
#define ROWS (B_*L_)          // 32768
#define QK_SCALE 0.35355339059327373f   // 1/sqrt(8)
#define LOG2E_F  1.4426950408889634f
#define NSL1 4                // key slices for pass1 (denominators)
#define SLK1 (L_/NSL1)        // 128 keys
#define NSL2 2                // key slices for pass2 (ctx partials)
#define SLK2 (L_/NSL2)        // 256 keys

typedef unsigned long long u64t;

// ---- packed f32x2 helpers (ptxas never auto-fuses; PTX only) ----
__device__ __forceinline__ u64t fma2(u64t a, u64t b, u64t c) {
    u64t d; asm("fma.rn.f32x2 %0, %1, %2, %3;" : "=l"(d) : "l"(a), "l"(b), "l"(c)); return d;
}
__device__ __forceinline__ u64t mul2(u64t a, u64t b) {
    u64t d; asm("mul.rn.f32x2 %0, %1, %2;" : "=l"(d) : "l"(a), "l"(b)); return d;
}
__device__ __forceinline__ u64t pack2(float lo, float hi) {
    u64t d; asm("mov.b64 %0, {%1, %2};" : "=l"(d) : "f"(lo), "f"(hi)); return d;
}
__device__ __forceinline__ void unpack2(u64t a, float& lo, float& hi) {
    asm("mov.b64 {%0, %1}, %2;" : "=f"(lo), "=f"(hi) : "l"(a));
}
__device__ __forceinline__ float ex2f(float x) {
    float r; asm("ex2.approx.f32 %0, %1;" : "=f"(r) : "f"(x)); return r;
}
__device__ __forceinline__ float lg2f(float x) {
    float r; asm("lg2.approx.f32 %0, %1;" : "=f"(r) : "f"(x)); return r;
}
__device__ __forceinline__ void barpair(int id) {
    asm volatile("bar.sync %0, 64;" :: "r"(id) : "memory");
}

// ---- scratch (static device arrays; no allocation) ----
__device__ float g_qh  [ROWS*E_];
__device__ float g_kh  [ROWS*E_];
__device__ float g_vh  [ROWS*E_];
__device__ float g_x   [ROWS*E_];
__device__ float g_p1  [ROWS*NSL1*H_];    // per-slice denominator partials
__device__ float g_ctxp[NSL2*ROWS*E_];    // per-slice ctx partials (16MB)

// ---------------------------------------------------------------------------
// GEMM compute core: xs[32][68], Ws[64][68] staged; 4x4 tile per thread,
// LDS.128 j-quad inner loop, packed fma2, 32-reg accumulators.
// ---------------------------------------------------------------------------
__device__ __forceinline__ void gemm_core(
    const float (*xs)[68], const float (*Ws)[68], int tx, int ty,
    u64t acc2[4][4])
{
#pragma unroll
    for (int rr = 0; rr < 4; rr++)
#pragma unroll
        for (int c = 0; c < 4; c++) acc2[rr][c] = 0ull;

#pragma unroll 4
    for (int j4 = 0; j4 < 16; j4++) {
        ulonglong2 xv[4], wv[4];
#pragma unroll
        for (int rr = 0; rr < 4; rr++)
            xv[rr] = *(const ulonglong2*)&xs[ty * 4 + rr][4 * j4];
#pragma unroll
        for (int c = 0; c < 4; c++)
            wv[c] = *(const ulonglong2*)&Ws[tx + c * 16][4 * j4];
#pragma unroll
        for (int rr = 0; rr < 4; rr++)
#pragma unroll
            for (int c = 0; c < 4; c++) {
                acc2[rr][c] = fma2(xv[rr].x, wv[c].x, acc2[rr][c]);
                acc2[rr][c] = fma2(xv[rr].y, wv[c].y, acc2[rr][c]);
            }
    }
}

// ---------------------------------------------------------------------------
// Fused q/k/v projection: blockIdx.y picks (X, W, bias, out, scale).
// W rows permuted at staging so output lands directly in [d*8+h] attn
// layout with coalesced stores. q pre-scaled by QK_SCALE*log2(e).
// ---------------------------------------------------------------------------
__global__ __launch_bounds__(128) void proj3(
    const float* __restrict__ q, const float* __restrict__ k,
    const float* __restrict__ Wq, const float* __restrict__ bq,
    const float* __restrict__ Wk, const float* __restrict__ bk,
    const float* __restrict__ Wv, const float* __restrict__ bv,
    float* __restrict__ qh, float* __restrict__ kh, float* __restrict__ vh)
{
    __shared__ float xs[32][68];
    __shared__ float Ws[64][68];

    const int t = threadIdx.x;
    const int which = blockIdx.y;
    const int rowbase = blockIdx.x * 32;

    const float* X    = (which == 0) ? q  : k;
    const float* W    = (which == 0) ? Wq : (which == 1) ? Wk : Wv;
    const float* bias = (which == 0) ? bq : (which == 1) ? bk : bv;
    float* Y          = (which == 0) ? qh : (which == 1) ? kh : vh;
    const float scale = (which == 0) ? QK_SCALE * LOG2E_F : 1.0f;

#pragma unroll
    for (int j = 0; j < 4; j++) {
        int fidx = t + j * 128;                  // 0..511
        int r = fidx >> 4, c = (fidx & 15) * 4;
        *(float4*)&xs[r][c] = ((const float4*)(X + (size_t)rowbase * 64))[fidx];
    }
    // Ws[r] = W[perm(r)]; perm(r) = (r&7)*8 + (r>>3)  (64B-coalesced loads)
#pragma unroll
    for (int j = 0; j < 8; j++) {
        int fidx = t + j * 128;                  // 0..1023
        int r = fidx >> 4, c = fidx & 15;
        int pr = (r & 7) * 8 + (r >> 3);
        *(float4*)&Ws[r][c * 4] = ((const float4*)W)[pr * 16 + c];
    }
    __syncthreads();

    const int tx = t & 15;
    const int ty = t >> 4;
    u64t acc2[4][4];
    gemm_core(xs, Ws, tx, ty, acc2);

#pragma unroll
    for (int c = 0; c < 4; c++) {
        int col = tx + c * 16;                   // already attn-layout column
        float bb = bias[(col & 7) * 8 + (col >> 3)];
#pragma unroll
        for (int rr = 0; rr < 4; rr++) {
            float lo, hi; unpack2(acc2[rr][c], lo, hi);
            Y[(size_t)(rowbase + ty * 4 + rr) * 64 + col] =
                scale * ((lo + hi) + bb);
        }
    }
}

// ---------------------------------------------------------------------------
// Fused GEMM + residual add + LayerNorm (Wo/ln1 path).
// out[r] = LN( sum_slices(ctxp)[r] @ W^T + bias + resid[r] )
// W's j index permuted at staging ([d*8+h] inputs).
// ---------------------------------------------------------------------------
__global__ __launch_bounds__(128) void gemm_ln(
    const float* __restrict__ X, const float* __restrict__ W,
    const float* __restrict__ bias, const float* __restrict__ resid,
    const float* __restrict__ g, const float* __restrict__ beta,
    float* __restrict__ out)
{
    __shared__ float xs[32][68];
    __shared__ float Ws[64][68];
    __shared__ float red[32][8];

    const int t = threadIdx.x;
    const int rowbase = blockIdx.x * 32;

    // xs[r][c] = sum over NSL2 slices of ctxp  (float4 granularity)
#pragma unroll
    for (int j = 0; j < 4; j++) {
        int fidx = t + j * 128;                  // 0..511 float4s
        size_t gf = (size_t)rowbase * 16 + fidx;
        float4 s = ((const float4*)X)[gf];
#pragma unroll
        for (int ss = 1; ss < NSL2; ss++) {
            float4 a = ((const float4*)X)[(size_t)ss * ROWS * 16 + gf];
            s.x += a.x; s.y += a.y; s.z += a.z; s.w += a.w;
        }
        int r = fidx >> 4, c = (fidx & 15) * 4;
        *(float4*)&xs[r][c] = s;
    }
    // W with permuted j (scalar gather)
#pragma unroll
    for (int kk = 0; kk < 32; kk++) {
        int idx = t + kk * 128;
        int r = idx >> 6, c = idx & 63;
        int cc = (c & 7) * 8 + (c >> 3);
        Ws[r][c] = W[r * 64 + cc];
    }
    __syncthreads();

    const int tx = t & 15;
    const int ty = t >> 4;
    u64t acc2[4][4];
    gemm_core(xs, Ws, tx, ty, acc2);

    __syncthreads();   // done reading xs; reuse it for the pre-LN values
#pragma unroll
    for (int c = 0; c < 4; c++) {
        int col = tx + c * 16;
        float bb = bias[col];
#pragma unroll
        for (int rr = 0; rr < 4; rr++) {
            float lo, hi; unpack2(acc2[rr][c], lo, hi);
            int row = ty * 4 + rr;
            xs[row][col] = (lo + hi) + bb +
                           resid[(size_t)(rowbase + row) * 64 + col];
        }
    }
    __syncthreads();

    // LN over each row of 64: 4 threads per row, 16 cols each
    const int row  = t >> 2;
    const int part = t & 3;
    float lsum = 0.0f, lsq = 0.0f;
#pragma unroll
    for (int j = 0; j < 16; j++) {
        float v = xs[row][part * 16 + j];
        lsum += v;
        lsq  = fmaf(v, v, lsq);
    }
    red[row][part]     = lsum;
    red[row][part + 4] = lsq;
    __syncthreads();

    float s  = red[row][0] + red[row][1] + red[row][2] + red[row][3];
    float sq = red[row][4] + red[row][5] + red[row][6] + red[row][7];
    float mu   = s * (1.0f / 64.0f);
    float var  = sq * (1.0f / 64.0f) - mu * mu;
    float rstd = rsqrtf(var + 1e-5f);

    float4 o[4];
#pragma unroll
    for (int j = 0; j < 16; j++) {
        int c = part * 16 + j;
        ((float*)o)[j] = fmaf((xs[row][c] - mu) * rstd, g[c], beta[c]);
    }
    float4* op = (float4*)(out + (size_t)(rowbase + row) * 64 + part * 16);
#pragma unroll
    for (int j = 0; j < 4; j++) op[j] = o[j];
}

// ---------------------------------------------------------------------------
// Fully fused FFN: out = LN2( relu(x@W1^T + b1) @ W2^T + b2 + x )
// One block = 32 rows. x, W1, W2 all staged up front; f1 lives only in smem.
// ---------------------------------------------------------------------------
__global__ __launch_bounds__(128) void ffn_fused(
    const float* __restrict__ X, const float* __restrict__ W1,
    const float* __restrict__ b1, const float* __restrict__ W2,
    const float* __restrict__ b2, const float* __restrict__ g,
    const float* __restrict__ beta, float* __restrict__ out)
{
    __shared__ float xs [32][68];
    __shared__ float fs [32][68];
    __shared__ float Ws1[64][68];
    __shared__ float Ws2[64][68];
    __shared__ float red[32][8];

    const int t = threadIdx.x;
    const int rowbase = blockIdx.x * 32;

#pragma unroll
    for (int j = 0; j < 4; j++) {
        int fidx = t + j * 128;
        int r = fidx >> 4, c = (fidx & 15) * 4;
        *(float4*)&xs[r][c] = ((const float4*)(X + (size_t)rowbase * 64))[fidx];
    }
#pragma unroll
    for (int j = 0; j < 8; j++) {
        int fidx = t + j * 128;
        int r = fidx >> 4, c = (fidx & 15) * 4;
        *(float4*)&Ws1[r][c] = ((const float4*)W1)[fidx];
        *(float4*)&Ws2[r][c] = ((const float4*)W2)[fidx];
    }
    __syncthreads();

    const int tx = t & 15;
    const int ty = t >> 4;
    u64t acc2[4][4];

    // f1 = relu(x @ W1^T + b1)  -> fs
    gemm_core(xs, Ws1, tx, ty, acc2);
#pragma unroll
    for (int c = 0; c < 4; c++) {
        int col = tx + c * 16;
        float bb = b1[col];
#pragma unroll
        for (int rr = 0; rr < 4; rr++) {
            float lo, hi; unpack2(acc2[rr][c], lo, hi);
            fs[ty * 4 + rr][col] = fmaxf((lo + hi) + bb, 0.0f);
        }
    }
    __syncthreads();

    // y = f1 @ W2^T + b2 + x   -> fs (after all reads complete)
    gemm_core(fs, Ws2, tx, ty, acc2);
    __syncthreads();
#pragma unroll
    for (int c = 0; c < 4; c++) {
        int col = tx + c * 16;
        float bb = b2[col];
#pragma unroll
        for (int rr = 0; rr < 4; rr++) {
            float lo, hi; unpack2(acc2[rr][c], lo, hi);
            int row = ty * 4 + rr;
            fs[row][col] = (lo + hi) + bb + xs[row][col];
        }
    }
    __syncthreads();

    // LN over each row of 64: 4 threads per row, 16 cols each
    const int row  = t >> 2;
    const int part = t & 3;
    float lsum = 0.0f, lsq = 0.0f;
#pragma unroll
    for (int j = 0; j < 16; j++) {
        float v = fs[row][part * 16 + j];
        lsum += v;
        lsq  = fmaf(v, v, lsq);
    }
    red[row][part]     = lsum;
    red[row][part + 4] = lsq;
    __syncthreads();

    float s  = red[row][0] + red[row][1] + red[row][2] + red[row][3];
    float sq = red[row][4] + red[row][5] + red[row][6] + red[row][7];
    float mu   = s * (1.0f / 64.0f);
    float var  = sq * (1.0f / 64.0f) - mu * mu;
    float rstd = rsqrtf(var + 1e-5f);

    float4 o[4];
#pragma unroll
    for (int j = 0; j < 16; j++) {
        int c = part * 16 + j;
        ((float*)o)[j] = fmaf((fs[row][c] - mu) * rstd, g[c], beta[c]);
    }
    float4* op = (float4*)(out + (size_t)(rowbase + row) * 64 + part * 16);
#pragma unroll
    for (int j = 0; j < 4; j++) op[j] = o[j];
}

// ---------------------------------------------------------------------------
// Attention pass 1: per-slice softmax denominator partials.
// Block 128 thr = 4 warps: warp = qg*2 + hh. Lane owns TWO queries, 4 heads.
// Whole 128-key slice staged once (32KB). Grid (L/128, NSL1, B).
// ---------------------------------------------------------------------------
__global__ __launch_bounds__(128) void attn_pass1(
    const float* __restrict__ qh, const float* __restrict__ kh,
    float* __restrict__ part)
{
    __shared__ float Ks[SLK1 * 64];   // 32KB

    const int b    = blockIdx.z;
    const int sl   = blockIdx.y;
    const int tid  = threadIdx.x;
    const int warp = tid >> 5;
    const int lane = tid & 31;
    const int qg   = warp >> 1;
    const int hh   = warp & 1;
    const size_t qi0 = (size_t)b * L_ + blockIdx.x * 128 + qg * 64 + lane;
    const size_t qi1 = qi0 + 32;

    u64t qa[16], qb[16];
    {
        const float* qp0 = qh + qi0 * 64 + hh * 4;
        const float* qp1 = qh + qi1 * 64 + hh * 4;
#pragma unroll
        for (int d = 0; d < 8; d++) {
            ulonglong2 v0 = *(const ulonglong2*)(qp0 + d * 8);
            ulonglong2 v1 = *(const ulonglong2*)(qp1 + d * 8);
            qa[2 * d] = v0.x; qa[2 * d + 1] = v0.y;
            qb[2 * d] = v1.x; qb[2 * d + 1] = v1.y;
        }
    }

    {
        const float4* src =
            (const float4*)(kh + ((size_t)b * L_ + sl * SLK1) * 64);
        float4* dst = (float4*)Ks;
#pragma unroll
        for (int j = 0; j < 16; j++)
            dst[tid + j * 128] = src[tid + j * 128];
    }
    __syncthreads();

    float sa[4] = {0.0f, 0.0f, 0.0f, 0.0f};
    float sb[4] = {0.0f, 0.0f, 0.0f, 0.0f};

#pragma unroll 2
    for (int m = 0; m < SLK1; m++) {
        const float* krow = Ks + m * 64 + hh * 4;
        u64t a0, a1, b0, b1;
        {
            ulonglong2 kd = *(const ulonglong2*)krow;
            a0 = mul2(qa[0], kd.x); a1 = mul2(qa[1], kd.y);
            b0 = mul2(qb[0], kd.x); b1 = mul2(qb[1], kd.y);
        }
#pragma unroll
        for (int d = 1; d < 8; d++) {
            ulonglong2 kd = *(const ulonglong2*)(krow + d * 8);
            a0 = fma2(qa[2 * d],     kd.x, a0);
            a1 = fma2(qa[2 * d + 1], kd.y, a1);
            b0 = fma2(qb[2 * d],     kd.x, b0);
            b1 = fma2(qb[2 * d + 1], kd.y, b1);
        }
        float lo, hi;
        unpack2(a0, lo, hi); sa[0] += ex2f(lo); sa[1] += ex2f(hi);
        unpack2(a1, lo, hi); sa[2] += ex2f(lo); sa[3] += ex2f(hi);
        unpack2(b0, lo, hi); sb[0] += ex2f(lo); sb[1] += ex2f(hi);
        unpack2(b1, lo, hi); sb[2] += ex2f(lo); sb[3] += ex2f(hi);
    }

    ((float4*)(part + qi0 * (NSL1 * 8) + sl * 8 + hh * 4))[0] =
        make_float4(sa[0], sa[1], sa[2], sa[3]);
    ((float4*)(part + qi1 * (NSL1 * 8) + sl * 8 + hh * 4))[0] =
        make_float4(sb[0], sb[1], sb[2], sb[3]);
}

// ---------------------------------------------------------------------------
// Attention pass 2: per-slice NORMALIZED ctx partials + fp32 attn_wts.
// warp = qg*2 + hh; lane owns one query, 4 heads. li = -log2(denom) folded
// into QK accumulator init => ex2 yields normalized p. 64-key K+V tiles.
// NSL2=2 slices (256 keys each). Head-half combine for attn_wts per
// warp-PAIR with 64-thread named barriers.
// ---------------------------------------------------------------------------
__global__ __launch_bounds__(256) void attn_pass2(
    const float* __restrict__ qh, const float* __restrict__ kh,
    const float* __restrict__ vh, const float* __restrict__ part,
    float* __restrict__ ctxp, float* __restrict__ attn_out)
{
    __shared__ float Ks[64 * 64];          // 16KB
    __shared__ float Vs[64 * 64];          // 16KB
    __shared__ float Wtile[8][32][17];     // 17.4KB

    const int b    = blockIdx.z;
    const int sl   = blockIdx.y;
    const int tid  = threadIdx.x;
    const int warp = tid >> 5;
    const int lane = tid & 31;
    const int qg   = warp >> 1;
    const int hh   = warp & 1;
    const int lt   = tid & 63;             // id within warp-pair
    const size_t qi = (size_t)b * L_ + blockIdx.x * 128 + qg * 32 + lane;

    u64t q2[16];
    {
        const float* qp = qh + qi * 64 + hh * 4;
#pragma unroll
        for (int d = 0; d < 8; d++) {
            ulonglong2 v = *(const ulonglong2*)(qp + d * 8);
            q2[2 * d] = v.x; q2[2 * d + 1] = v.y;
        }
    }

    u64t li2[2];
    {
        float s[4] = {0.0f, 0.0f, 0.0f, 0.0f};
        const float4* pp = (const float4*)(part + qi * (NSL1 * 8));
#pragma unroll
        for (int ss = 0; ss < NSL1; ss++) {
            float4 a = pp[2 * ss + hh];
            s[0] += a.x; s[1] += a.y; s[2] += a.z; s[3] += a.w;
        }
        li2[0] = pack2(-lg2f(s[0]), -lg2f(s[1]));
        li2[1] = pack2(-lg2f(s[2]), -lg2f(s[3]));
    }

    u64t ctx2[16];
#pragma unroll
    for (int j = 0; j < 16; j++) ctx2[j] = 0ull;

    for (int t = 0; t < SLK2 / 64; t++) {
        __syncthreads();
        {
            const size_t rowb = ((size_t)b * L_ + sl * SLK2 + t * 64) * 16;
            const float4* ksrc = (const float4*)kh + rowb;
            const float4* vsrc = (const float4*)vh + rowb;
            float4* kdst = (float4*)Ks;
            float4* vdst = (float4*)Vs;
#pragma unroll
            for (int j = 0; j < 4; j++) {
                kdst[tid + j * 256] = ksrc[tid + j * 256];
                vdst[tid + j * 256] = vsrc[tid + j * 256];
            }
        }
        __syncthreads();

        for (int chunk = 0; chunk < 4; chunk++) {
#pragma unroll 2
            for (int mm = 0; mm < 16; mm++) {
                const int m = chunk * 16 + mm;
                const float* krow = Ks + m * 64 + hh * 4;
                u64t acc0 = li2[0], acc1 = li2[1];
#pragma unroll
                for (int d = 0; d < 8; d++) {
                    ulonglong2 kd = *(const ulonglong2*)(krow + d * 8);
                    acc0 = fma2(q2[2 * d],     kd.x, acc0);
                    acc1 = fma2(q2[2 * d + 1], kd.y, acc1);
                }
                float e0, e1, e2v, e3v;
                { float lo, hi; unpack2(acc0, lo, hi); e0 = ex2f(lo); e1 = ex2f(hi); }
                { float lo, hi; unpack2(acc1, lo, hi); e2v = ex2f(lo); e3v = ex2f(hi); }
                Wtile[warp][lane][mm] = (e0 + e1) + (e2v + e3v);

                u64t ep0 = pack2(e0, e1), ep1 = pack2(e2v, e3v);
                const float* vrow = Vs + m * 64 + hh * 4;
#pragma unroll
                for (int d = 0; d < 8; d++) {
                    ulonglong2 vd = *(const ulonglong2*)(vrow + d * 8);
                    ctx2[2 * d]     = fma2(ep0, vd.x, ctx2[2 * d]);
                    ctx2[2 * d + 1] = fma2(ep1, vd.y, ctx2[2 * d + 1]);
                }
            }
            // pair-combine hh halves -> fp32 attn_out (64-thread barrier)
            barpair(1 + qg);
            {
                const int m0 = sl * SLK2 + t * 64 + chunk * 16;
                const size_t row0 = (size_t)b * L_ + blockIdx.x * 128 + qg * 32;
#pragma unroll
                for (int it = 0; it < 8; it++) {
                    int idx = lt + it * 64;             // 0..511
                    int c   = idx & 15;
                    int r   = idx >> 4;                 // 0..31
                    float w = (Wtile[qg * 2][r][c] + Wtile[qg * 2 + 1][r][c])
                              * 0.125f;
                    attn_out[(row0 + r) * L_ + m0 + c] = w;
                }
            }
            barpair(1 + qg);
        }
    }

    // store this half's normalized ctx partial (disjoint 16B chunks)
    float* cb = ctxp + (size_t)sl * ROWS * 64 + qi * 64 + hh * 4;
#pragma unroll
    for (int d = 0; d < 8; d++) {
        ulonglong2 v;
        v.x = ctx2[2 * d]; v.y = ctx2[2 * d + 1];
        *(ulonglong2*)(cb + d * 8) = v;
    }
}

// ---------------------------------------------------------------------------
extern "C" void kernel_launch(void* const* d_in, const int* in_sizes, int n_in,
                              void* d_out, int out_size)
{
    const float* q    = (const float*)d_in[0];
    const float* k    = (const float*)d_in[1];
    const float* prev = (const float*)d_in[2];
    const float* Wq   = (const float*)d_in[3];
    const float* bq   = (const float*)d_in[4];
    const float* Wk   = (const float*)d_in[5];
    const float* bk   = (const float*)d_in[6];
    const float* Wv   = (const float*)d_in[7];
    const float* bv   = (const float*)d_in[8];
    const float* Wo   = (const float*)d_in[9];
    const float* bo   = (const float*)d_in[10];
    const float* g1   = (const float*)d_in[11];
    const float* be1  = (const float*)d_in[12];
    const float* W1   = (const float*)d_in[13];
    const float* b1   = (const float*)d_in[14];
    const float* W2   = (const float*)d_in[15];
    const float* b2   = (const float*)d_in[16];
    const float* g2   = (const float*)d_in[17];
    const float* be2  = (const float*)d_in[18];

    float* outp = (float*)d_out;                    // [B, Lq, E]
    float* attn = outp + (size_t)ROWS * E_;         // [B, Lq, Lk]

    float *qh, *khp, *vhp, *xbuf, *p1, *ctxp;
    cudaGetSymbolAddress((void**)&qh,  g_qh);
    cudaGetSymbolAddress((void**)&khp, g_kh);
    cudaGetSymbolAddress((void**)&vhp, g_vh);
    cudaGetSymbolAddress((void**)&xbuf,g_x);
    cudaGetSymbolAddress((void**)&p1,  g_p1);
    cudaGetSymbolAddress((void**)&ctxp,g_ctxp);

    const int GB = ROWS / 32;   // 1024 blocks per gemm

    // fused q/k/v projections (one launch, 3072 blocks)
    proj3<<<dim3(GB, 3), 128>>>(q, k, Wq, bq, Wk, bk, Wv, bv, qh, khp, vhp);

    attn_pass1<<<dim3(L_ / 128, NSL1, B_), 128>>>(qh, khp, p1);
    attn_pass2<<<dim3(L_ / 128, NSL2, B_), 256>>>(qh, khp, vhp, p1, ctxp, attn);

    // Wo GEMM + ctx_combine + residual(prev) + LN1  -> xbuf
    gemm_ln<<<GB, 128>>>(ctxp, Wo, bo, prev, g1, be1, xbuf);

    // fully fused FFN + residual + LN2 -> final out
    ffn_fused<<<GB, 128>>>(xbuf, W1, b1, W2, b2, g2, be2, outp);
}